// round 6
// baseline (speedup 1.0000x reference)
#include <cuda_runtime.h>
#include <cuda_bf16.h>
#include <cstdint>

#define S_LEN 2048
#define NBATCH 4
#define EMB 1024
#define NH 16
#define HD 64

// ---------------------------------------------------------------------------
// Scratch (allocation-free rule: __device__ globals)
// ---------------------------------------------------------------------------
__device__ float g_q[NBATCH * S_LEN * EMB];
__device__ float g_k[NBATCH * S_LEN * EMB];
__device__ float g_v[NBATCH * S_LEN * EMB];
__device__ float g_att[NBATCH * S_LEN * EMB];
__device__ __nv_bfloat16 g_wt_hi[4 * EMB * EMB];   // W^T split high, [4][N][K]
__device__ __nv_bfloat16 g_wt_lo[4 * EMB * EMB];   // W^T split low
__device__ __nv_bfloat16 g_a_hi[NBATCH * S_LEN * EMB];  // activation split high
__device__ __nv_bfloat16 g_a_lo[NBATCH * S_LEN * EMB];  // activation split low

// ---------------------------------------------------------------------------
// Base-ISA PTX helpers (no tcgen05 — harness PTX target is plain sm_103)
// ---------------------------------------------------------------------------
__device__ __forceinline__ uint32_t smem_to_u32(const void* p) {
    uint32_t a;
    asm("{ .reg .u64 t; cvta.to.shared.u64 t, %1; cvt.u32.u64 %0, t; }"
        : "=r"(a) : "l"(p));
    return a;
}

__device__ __forceinline__ void ldsm_x4(uint32_t* r, uint32_t addr) {
    asm volatile("ldmatrix.sync.aligned.m8n8.x4.shared.b16 {%0,%1,%2,%3}, [%4];"
                 : "=r"(r[0]), "=r"(r[1]), "=r"(r[2]), "=r"(r[3]) : "r"(addr));
}

__device__ __forceinline__ void mma_bf16(float* d, const uint32_t* a,
                                         uint32_t b0, uint32_t b1) {
    asm volatile(
        "mma.sync.aligned.m16n8k16.row.col.f32.bf16.bf16.f32 "
        "{%0,%1,%2,%3}, {%4,%5,%6,%7}, {%8,%9}, {%0,%1,%2,%3};"
        : "+f"(d[0]), "+f"(d[1]), "+f"(d[2]), "+f"(d[3])
        : "r"(a[0]), "r"(a[1]), "r"(a[2]), "r"(a[3]), "r"(b0), "r"(b1));
}

__device__ __forceinline__ void cp16(uint32_t s, const void* g) {
    asm volatile("cp.async.cg.shared.global [%0], [%1], 16;" :: "r"(s), "l"(g));
}
__device__ __forceinline__ void cp_commit() {
    asm volatile("cp.async.commit_group;" ::: "memory");
}
template <int N>
__device__ __forceinline__ void cp_wait() {
    asm volatile("cp.async.wait_group %0;" :: "n"(N) : "memory");
}

// ---------------------------------------------------------------------------
// Weight transpose + split: W[K][N] fp32 -> Wt_hi/Wt_lo[N][K] bf16
// ---------------------------------------------------------------------------
__global__ void transpose_split(const float* __restrict__ W,
                                __nv_bfloat16* __restrict__ Th,
                                __nv_bfloat16* __restrict__ Tl)
{
    __shared__ float t[32][33];
    const int tx = threadIdx.x, ty = threadIdx.y;
    const int bx = blockIdx.x * 32, by = blockIdx.y * 32;
#pragma unroll
    for (int j = 0; j < 4; j++)
        t[ty + j * 8][tx] = W[(size_t)(by + ty + j * 8) * EMB + bx + tx];
    __syncthreads();
#pragma unroll
    for (int j = 0; j < 4; j++) {
        float v = t[tx][ty + j * 8];
        __nv_bfloat16 hi = __float2bfloat16_rn(v);
        __nv_bfloat16 lo = __float2bfloat16_rn(v - __bfloat162float(hi));
        const size_t o = (size_t)(bx + ty + j * 8) * EMB + by + tx;
        Th[o] = hi;
        Tl[o] = lo;
    }
}

// ---------------------------------------------------------------------------
// Activation split: X fp32 -> hi/lo bf16 (elementwise)
// ---------------------------------------------------------------------------
union B4 { __nv_bfloat16 b[4]; uint2 u; };

__global__ __launch_bounds__(256)
void split2(const float* __restrict__ X, __nv_bfloat16* __restrict__ H,
            __nv_bfloat16* __restrict__ L)
{
    const int i = blockIdx.x * 256 + threadIdx.x;   // float4 index
    float4 v = ((const float4*)X)[i];
    float f[4] = {v.x, v.y, v.z, v.w};
    B4 h, l;
#pragma unroll
    for (int j = 0; j < 4; j++) {
        h.b[j] = __float2bfloat16_rn(f[j]);
        l.b[j] = __float2bfloat16_rn(f[j] - __bfloat162float(h.b[j]));
    }
    ((uint2*)H)[i] = h.u;
    ((uint2*)L)[i] = l.u;
}

// ---------------------------------------------------------------------------
// mma.sync split-bf16 GEMM: C[M,1024] = A @ W + bias  (fp32-accurate)
// A pre-split hi/lo [M][K] bf16, W pre-transposed+split [N][K] bf16.
// 128x128 block, BK=32, 8 warps (64x32 each), cp.async double buffer.
// ---------------------------------------------------------------------------
#define LDT 40                       // smem row stride (bf16 elems), conflict-free
#define TBY (128 * LDT * 2)          // one tile: 10240 bytes
#define BUFB (4 * TBY)               // Ahi|Alo|Bhi|Blo per buffer

__global__ __launch_bounds__(256, 2)
void gemm_ms(const __nv_bfloat16* __restrict__ Ahi,
             const __nv_bfloat16* __restrict__ Alo,
             const __nv_bfloat16* __restrict__ Bhi,
             const __nv_bfloat16* __restrict__ Blo,
             const float* __restrict__ bias, float* __restrict__ C)
{
    extern __shared__ char smc[];
    const uint32_t sb = smem_to_u32(smc);
    const int tid = threadIdx.x;
    const int wid = tid >> 5, lane = tid & 31;
    const int m0 = blockIdx.y * 128, n0 = blockIdx.x * 128;

    // ---- async load helper data: chunk c in [0,512): row=c>>2, c4=c&3 ----
    const __nv_bfloat16* gp[4] = {Ahi, Alo, Bhi, Blo};
    const int gbase[4] = {m0, m0, n0, n0};

    // ---- ldmatrix lane offset ----
    const int lrow = (lane & 7) + ((lane >> 3) & 1) * 8;
    const int lcol = (lane >> 4) * 8;
    const uint32_t laneoff = (uint32_t)(lrow * (LDT * 2) + lcol * 2);

    const int wm = (wid & 1) * 64;
    const int wn = (wid >> 1) * 32;

    float acc[4][4][4];
#pragma unroll
    for (int i = 0; i < 4; i++)
#pragma unroll
        for (int j = 0; j < 4; j++)
#pragma unroll
            for (int e = 0; e < 4; e++) acc[i][j][e] = 0.0f;

    // ---- prologue: issue buffer 0 (kc = 0) ----
#pragma unroll
    for (int arr = 0; arr < 4; arr++) {
#pragma unroll
        for (int h = 0; h < 2; h++) {
            const int c = tid + h * 256;
            const int row = c >> 2, c4 = c & 3;
            cp16(sb + arr * TBY + row * (LDT * 2) + c4 * 16,
                 gp[arr] + (size_t)(gbase[arr] + row) * EMB + c4 * 8);
        }
    }
    cp_commit();

    const int NKC = EMB / 32;   // 32
    for (int kc = 0; kc < NKC; kc++) {
        const int buf = kc & 1;
        // issue next buffer
        if (kc + 1 < NKC) {
            const uint32_t so = sb + (buf ^ 1) * BUFB;
            const int koff = (kc + 1) * 32;
#pragma unroll
            for (int arr = 0; arr < 4; arr++) {
#pragma unroll
                for (int h = 0; h < 2; h++) {
                    const int c = tid + h * 256;
                    const int row = c >> 2, c4 = c & 3;
                    cp16(so + arr * TBY + row * (LDT * 2) + c4 * 16,
                         gp[arr] + (size_t)(gbase[arr] + row) * EMB + koff + c4 * 8);
                }
            }
            cp_commit();
            cp_wait<1>();
        } else {
            cp_wait<0>();
        }
        __syncthreads();

        const uint32_t tb = sb + buf * BUFB;
#pragma unroll
        for (int ks = 0; ks < 32; ks += 16) {
            uint32_t ah[4][4], al[4][4];
#pragma unroll
            for (int i = 0; i < 4; i++) {
                const uint32_t ao = tb + (wm + i * 16) * (LDT * 2) + ks * 2 + laneoff;
                ldsm_x4(ah[i], ao);
                ldsm_x4(al[i], ao + TBY);
            }
            uint32_t b0[4], b1[4];
            {
                const uint32_t bo = tb + 2 * TBY + wn * (LDT * 2) + ks * 2 + laneoff;
                ldsm_x4(b0, bo);
                ldsm_x4(b1, bo + 16 * (LDT * 2));
            }
            // products: Ahi*Bhi and Alo*Bhi
#pragma unroll
            for (int i = 0; i < 4; i++) {
                mma_bf16(acc[i][0], ah[i], b0[0], b0[2]);
                mma_bf16(acc[i][1], ah[i], b0[1], b0[3]);
                mma_bf16(acc[i][2], ah[i], b1[0], b1[2]);
                mma_bf16(acc[i][3], ah[i], b1[1], b1[3]);
            }
#pragma unroll
            for (int i = 0; i < 4; i++) {
                mma_bf16(acc[i][0], al[i], b0[0], b0[2]);
                mma_bf16(acc[i][1], al[i], b0[1], b0[3]);
                mma_bf16(acc[i][2], al[i], b1[0], b1[2]);
                mma_bf16(acc[i][3], al[i], b1[1], b1[3]);
            }
            // reload B as lo, product Ahi*Blo
            {
                const uint32_t bo = tb + 3 * TBY + wn * (LDT * 2) + ks * 2 + laneoff;
                ldsm_x4(b0, bo);
                ldsm_x4(b1, bo + 16 * (LDT * 2));
            }
#pragma unroll
            for (int i = 0; i < 4; i++) {
                mma_bf16(acc[i][0], ah[i], b0[0], b0[2]);
                mma_bf16(acc[i][1], ah[i], b0[1], b0[3]);
                mma_bf16(acc[i][2], ah[i], b1[0], b1[2]);
                mma_bf16(acc[i][3], ah[i], b1[1], b1[3]);
            }
        }
        __syncthreads();
    }

    // ---- epilogue: bias + store ----
#pragma unroll
    for (int i = 0; i < 4; i++) {
        const int r = m0 + wm + i * 16 + (lane >> 2);
#pragma unroll
        for (int j = 0; j < 4; j++) {
            const int c = n0 + wn + j * 8 + (lane & 3) * 2;
            const float2 bv = *(const float2*)(bias + c);
            float2 o0, o1;
            o0.x = acc[i][j][0] + bv.x;
            o0.y = acc[i][j][1] + bv.y;
            o1.x = acc[i][j][2] + bv.x;
            o1.y = acc[i][j][3] + bv.y;
            *(float2*)(C + (size_t)r * EMB + c) = o0;
            *(float2*)(C + (size_t)(r + 8) * EMB + c) = o1;
        }
    }
}

// ---------------------------------------------------------------------------
// Flash attention, fp32 (unchanged — proven correct, round-2)
// ---------------------------------------------------------------------------
#define BQ 64
#define BKT 64
#define DP 68

__global__ __launch_bounds__(256)
void attn_kernel(const float* __restrict__ Q, const float* __restrict__ Kt,
                 const float* __restrict__ V, const int* __restrict__ mask,
                 float* __restrict__ Out)
{
    extern __shared__ float sm[];
    float (*Qs)[DP]  = (float(*)[DP])sm;
    float (*KPs)[DP] = (float(*)[DP])(sm + HD * DP);
    float (*Vs)[DP]  = (float(*)[DP])(sm + 2 * HD * DP);

    const int tid = threadIdx.x;
    const int tx = tid & 15;
    const int ty = tid >> 4;
    const int qb = blockIdx.x;
    const int h  = blockIdx.y;
    const int n  = blockIdx.z;

    const int q0 = qb * BQ;
    const size_t base = ((size_t)n * S_LEN) * EMB + (size_t)h * HD;

    {
        const int tok = tid >> 2;
        const int d0 = (tid & 3) * 16;
        const float* src = Q + base + (size_t)(q0 + tok) * EMB + d0;
#pragma unroll
        for (int u = 0; u < 4; u++) {
            float4 v = *(const float4*)(src + u * 4);
            Qs[d0 + u * 4 + 0][tok] = v.x * 0.03125f;
            Qs[d0 + u * 4 + 1][tok] = v.y * 0.03125f;
            Qs[d0 + u * 4 + 2][tok] = v.z * 0.03125f;
            Qs[d0 + u * 4 + 3][tok] = v.w * 0.03125f;
        }
    }

    float o[4][4] = {};
    float mrow[4], lrow[4];
#pragma unroll
    for (int i = 0; i < 4; i++) { mrow[i] = -3.0e38f; lrow[i] = 0.0f; }

    for (int kt = 0; kt < S_LEN / BKT; kt++) {
        const int k0 = kt * BKT;
        __syncthreads();
        {
            const int tok = tid >> 2;
            const int d0 = (tid & 3) * 16;
            const float* ksrc = Kt + base + (size_t)(k0 + tok) * EMB + d0;
            const float* vsrc = V  + base + (size_t)(k0 + tok) * EMB + d0;
#pragma unroll
            for (int u = 0; u < 4; u++) {
                float4 kv = *(const float4*)(ksrc + u * 4);
                KPs[d0 + u * 4 + 0][tok] = kv.x;
                KPs[d0 + u * 4 + 1][tok] = kv.y;
                KPs[d0 + u * 4 + 2][tok] = kv.z;
                KPs[d0 + u * 4 + 3][tok] = kv.w;
                *(float4*)&Vs[tok][d0 + u * 4] = *(const float4*)(vsrc + u * 4);
            }
        }
        __syncthreads();

        float s[4][4] = {};
#pragma unroll 8
        for (int d = 0; d < HD; d++) {
            float4 a = *(const float4*)&Qs[d][ty * 4];
            float4 b = *(const float4*)&KPs[d][tx * 4];
            float av[4] = {a.x, a.y, a.z, a.w};
            float bv[4] = {b.x, b.y, b.z, b.w};
#pragma unroll
            for (int i = 0; i < 4; i++)
#pragma unroll
                for (int j = 0; j < 4; j++)
                    s[i][j] += av[i] * bv[j];
        }

        {
            const int* mp = mask + n * S_LEN + k0 + tx * 4;
#pragma unroll
            for (int j = 0; j < 4; j++) {
                if (mp[j] == 0) {
                    s[0][j] = -1e20f; s[1][j] = -1e20f;
                    s[2][j] = -1e20f; s[3][j] = -1e20f;
                }
            }
        }

        float p[4][4];
#pragma unroll
        for (int i = 0; i < 4; i++) {
            float rm = fmaxf(fmaxf(s[i][0], s[i][1]), fmaxf(s[i][2], s[i][3]));
#pragma unroll
            for (int off = 8; off >= 1; off >>= 1)
                rm = fmaxf(rm, __shfl_xor_sync(0xffffffffu, rm, off, 16));
            const float mnew = fmaxf(mrow[i], rm);
            const float corr = __expf(mrow[i] - mnew);
            mrow[i] = mnew;
            float ls = 0.0f;
#pragma unroll
            for (int j = 0; j < 4; j++) {
                p[i][j] = __expf(s[i][j] - mnew);
                ls += p[i][j];
            }
#pragma unroll
            for (int off = 8; off >= 1; off >>= 1)
                ls += __shfl_xor_sync(0xffffffffu, ls, off, 16);
            lrow[i] = lrow[i] * corr + ls;
#pragma unroll
            for (int j = 0; j < 4; j++) o[i][j] *= corr;
        }

        __syncthreads();
#pragma unroll
        for (int i = 0; i < 4; i++)
#pragma unroll
            for (int j = 0; j < 4; j++)
                KPs[ty * 4 + i][tx * 4 + j] = p[i][j];
        __syncthreads();

#pragma unroll 8
        for (int k = 0; k < BKT; k++) {
            float4 vv = *(const float4*)&Vs[k][tx * 4];
#pragma unroll
            for (int i = 0; i < 4; i++) {
                const float pv = KPs[ty * 4 + i][k];
                o[i][0] += pv * vv.x;
                o[i][1] += pv * vv.y;
                o[i][2] += pv * vv.z;
                o[i][3] += pv * vv.w;
            }
        }
    }

#pragma unroll
    for (int i = 0; i < 4; i++) {
        const float inv = 1.0f / lrow[i];
        float4 ov = make_float4(o[i][0] * inv, o[i][1] * inv,
                                o[i][2] * inv, o[i][3] * inv);
        *(float4*)(Out + base + (size_t)(q0 + ty * 4 + i) * EMB + tx * 4) = ov;
    }
}

// ---------------------------------------------------------------------------
extern "C" void kernel_launch(void* const* d_in, const int* in_sizes, int n_in,
                              void* d_out, int out_size)
{
    const float* values = (const float*)d_in[0];
    const float* keys   = (const float*)d_in[1];
    const float* query  = (const float*)d_in[2];
    const int*   mask   = (const int*)  d_in[3];
    const float* Wv = (const float*)d_in[4];
    const float* bv = (const float*)d_in[5];
    const float* Wk = (const float*)d_in[6];
    const float* bk = (const float*)d_in[7];
    const float* Wq = (const float*)d_in[8];
    const float* bq = (const float*)d_in[9];
    const float* Wo = (const float*)d_in[10];
    const float* bo = (const float*)d_in[11];
    float* out = (float*)d_out;

    float *q, *k, *v, *att;
    __nv_bfloat16 *wth, *wtl, *ahi, *alo;
    cudaGetSymbolAddress((void**)&q,   g_q);
    cudaGetSymbolAddress((void**)&k,   g_k);
    cudaGetSymbolAddress((void**)&v,   g_v);
    cudaGetSymbolAddress((void**)&att, g_att);
    cudaGetSymbolAddress((void**)&wth, g_wt_hi);
    cudaGetSymbolAddress((void**)&wtl, g_wt_lo);
    cudaGetSymbolAddress((void**)&ahi, g_a_hi);
    cudaGetSymbolAddress((void**)&alo, g_a_lo);

    const int gemm_smem = 2 * BUFB;                          // 81920 B
    cudaFuncSetAttribute(gemm_ms,
                         cudaFuncAttributeMaxDynamicSharedMemorySize, gemm_smem);
    const int attn_smem = 3 * HD * DP * (int)sizeof(float);  // 52224 B
    cudaFuncSetAttribute(attn_kernel,
                         cudaFuncAttributeMaxDynamicSharedMemorySize, attn_smem);

    const size_t WSZ = (size_t)EMB * EMB;
    const int M = NBATCH * S_LEN;                            // 8192
    dim3 tgrid(32, 32), tblk(32, 8);
    transpose_split<<<tgrid, tblk>>>(Wq, wth + 0 * WSZ, wtl + 0 * WSZ);
    transpose_split<<<tgrid, tblk>>>(Wk, wth + 1 * WSZ, wtl + 1 * WSZ);
    transpose_split<<<tgrid, tblk>>>(Wv, wth + 2 * WSZ, wtl + 2 * WSZ);
    transpose_split<<<tgrid, tblk>>>(Wo, wth + 3 * WSZ, wtl + 3 * WSZ);

    const int splitg = (M * EMB / 4) / 256;                  // 8192 blocks
    dim3 ggrid(EMB / 128, M / 128);                          // (8, 64)

    split2<<<splitg, 256>>>(query, ahi, alo);
    gemm_ms<<<ggrid, 256, gemm_smem>>>(ahi, alo, wth + 0 * WSZ, wtl + 0 * WSZ, bq, q);
    split2<<<splitg, 256>>>(keys, ahi, alo);
    gemm_ms<<<ggrid, 256, gemm_smem>>>(ahi, alo, wth + 1 * WSZ, wtl + 1 * WSZ, bk, k);
    split2<<<splitg, 256>>>(values, ahi, alo);
    gemm_ms<<<ggrid, 256, gemm_smem>>>(ahi, alo, wth + 2 * WSZ, wtl + 2 * WSZ, bv, v);

    dim3 agrid(S_LEN / BQ, NH, NBATCH);                      // (32, 16, 4)
    attn_kernel<<<agrid, 256, attn_smem>>>(q, k, v, mask, att);

    split2<<<splitg, 256>>>(att, ahi, alo);
    gemm_ms<<<ggrid, 256, gemm_smem>>>(ahi, alo, wth + 3 * WSZ, wtl + 3 * WSZ, bo, out);
}

// round 7
// speedup vs baseline: 2.7170x; 2.7170x over previous
#include <cuda_runtime.h>
#include <cuda_bf16.h>
#include <cuda_fp16.h>
#include <cstdint>

#define S_LEN 2048
#define NBATCH 4
#define EMB 1024
#define NH 16
#define HD 64

// ---------------------------------------------------------------------------
// Scratch (allocation-free rule: __device__ globals)
// ---------------------------------------------------------------------------
__device__ __nv_bfloat16 g_wt_hi[4 * EMB * EMB];        // W^T split high [4][N][K]
__device__ __nv_bfloat16 g_wt_lo[4 * EMB * EMB];        // W^T split low
__device__ __nv_bfloat16 g_a_hi[NBATCH * S_LEN * EMB];  // activation split high
__device__ __nv_bfloat16 g_a_lo[NBATCH * S_LEN * EMB];  // activation split low
__device__ __half g_qh[NBATCH * S_LEN * EMB];           // q (pre-scaled 1/32) fp16
__device__ __half g_kh[NBATCH * S_LEN * EMB];           // k fp16
__device__ __half g_vh[NBATCH * S_LEN * EMB];           // v fp16

// ---------------------------------------------------------------------------
// Base-ISA PTX helpers (harness PTX target is plain sm_103 — no tcgen05)
// ---------------------------------------------------------------------------
__device__ __forceinline__ uint32_t smem_to_u32(const void* p) {
    uint32_t a;
    asm("{ .reg .u64 t; cvta.to.shared.u64 t, %1; cvt.u32.u64 %0, t; }"
        : "=r"(a) : "l"(p));
    return a;
}

__device__ __forceinline__ void ldsm_x4(uint32_t* r, uint32_t addr) {
    asm volatile("ldmatrix.sync.aligned.m8n8.x4.shared.b16 {%0,%1,%2,%3}, [%4];"
                 : "=r"(r[0]), "=r"(r[1]), "=r"(r[2]), "=r"(r[3]) : "r"(addr));
}
__device__ __forceinline__ void ldsm_x4_t(uint32_t* r, uint32_t addr) {
    asm volatile("ldmatrix.sync.aligned.m8n8.x4.trans.shared.b16 {%0,%1,%2,%3}, [%4];"
                 : "=r"(r[0]), "=r"(r[1]), "=r"(r[2]), "=r"(r[3]) : "r"(addr));
}

__device__ __forceinline__ void mma_bf16(float* d, const uint32_t* a,
                                         uint32_t b0, uint32_t b1) {
    asm volatile(
        "mma.sync.aligned.m16n8k16.row.col.f32.bf16.bf16.f32 "
        "{%0,%1,%2,%3}, {%4,%5,%6,%7}, {%8,%9}, {%0,%1,%2,%3};"
        : "+f"(d[0]), "+f"(d[1]), "+f"(d[2]), "+f"(d[3])
        : "r"(a[0]), "r"(a[1]), "r"(a[2]), "r"(a[3]), "r"(b0), "r"(b1));
}
__device__ __forceinline__ void mma_f16(float* d, const uint32_t* a,
                                        uint32_t b0, uint32_t b1) {
    asm volatile(
        "mma.sync.aligned.m16n8k16.row.col.f32.f16.f16.f32 "
        "{%0,%1,%2,%3}, {%4,%5,%6,%7}, {%8,%9}, {%0,%1,%2,%3};"
        : "+f"(d[0]), "+f"(d[1]), "+f"(d[2]), "+f"(d[3])
        : "r"(a[0]), "r"(a[1]), "r"(a[2]), "r"(a[3]), "r"(b0), "r"(b1));
}

__device__ __forceinline__ void cp16(uint32_t s, const void* g) {
    asm volatile("cp.async.cg.shared.global [%0], [%1], 16;" :: "r"(s), "l"(g));
}
__device__ __forceinline__ void cp_commit() {
    asm volatile("cp.async.commit_group;" ::: "memory");
}
template <int N>
__device__ __forceinline__ void cp_wait() {
    asm volatile("cp.async.wait_group %0;" :: "n"(N) : "memory");
}

__device__ __forceinline__ uint32_t packh2(float a, float b) {
    __half2 h = __floats2half2_rn(a, b);
    return *(uint32_t*)&h;
}

// ---------------------------------------------------------------------------
// Weight transpose + split: W[K][N] fp32 -> Wt_hi/Wt_lo[N][K] bf16
// ---------------------------------------------------------------------------
__global__ void transpose_split(const float* __restrict__ W,
                                __nv_bfloat16* __restrict__ Th,
                                __nv_bfloat16* __restrict__ Tl)
{
    __shared__ float t[32][33];
    const int tx = threadIdx.x, ty = threadIdx.y;
    const int bx = blockIdx.x * 32, by = blockIdx.y * 32;
#pragma unroll
    for (int j = 0; j < 4; j++)
        t[ty + j * 8][tx] = W[(size_t)(by + ty + j * 8) * EMB + bx + tx];
    __syncthreads();
#pragma unroll
    for (int j = 0; j < 4; j++) {
        float v = t[tx][ty + j * 8];
        __nv_bfloat16 hi = __float2bfloat16_rn(v);
        __nv_bfloat16 lo = __float2bfloat16_rn(v - __bfloat162float(hi));
        const size_t o = (size_t)(bx + ty + j * 8) * EMB + by + tx;
        Th[o] = hi;
        Tl[o] = lo;
    }
}

// ---------------------------------------------------------------------------
// Activation split: X fp32 -> hi/lo bf16 (elementwise)
// ---------------------------------------------------------------------------
union B4 { __nv_bfloat16 b[4]; uint2 u; };

__global__ __launch_bounds__(256)
void split2(const float* __restrict__ X, __nv_bfloat16* __restrict__ H,
            __nv_bfloat16* __restrict__ L)
{
    const int i = blockIdx.x * 256 + threadIdx.x;
    float4 v = ((const float4*)X)[i];
    float f[4] = {v.x, v.y, v.z, v.w};
    B4 h, l;
#pragma unroll
    for (int j = 0; j < 4; j++) {
        h.b[j] = __float2bfloat16_rn(f[j]);
        l.b[j] = __float2bfloat16_rn(f[j] - __bfloat162float(h.b[j]));
    }
    ((uint2*)H)[i] = h.u;
    ((uint2*)L)[i] = l.u;
}

// ---------------------------------------------------------------------------
// mma.sync split-bf16 GEMM (fp32-accurate). Template: fp32 or fp16 output.
// ---------------------------------------------------------------------------
#define LDT 40
#define TBY (128 * LDT * 2)
#define BUFB (4 * TBY)

template <bool HOUT>
__global__ __launch_bounds__(256, 2)
void gemm_ms(const __nv_bfloat16* __restrict__ Ahi,
             const __nv_bfloat16* __restrict__ Alo,
             const __nv_bfloat16* __restrict__ Bhi,
             const __nv_bfloat16* __restrict__ Blo,
             const float* __restrict__ bias, float scale,
             float* __restrict__ Cf, __half* __restrict__ Ch)
{
    extern __shared__ char smc[];
    const uint32_t sb = smem_to_u32(smc);
    const int tid = threadIdx.x;
    const int wid = tid >> 5, lane = tid & 31;
    const int m0 = blockIdx.y * 128, n0 = blockIdx.x * 128;

    const __nv_bfloat16* gp[4] = {Ahi, Alo, Bhi, Blo};
    const int gbase[4] = {m0, m0, n0, n0};

    const int lrow = (lane & 7) + ((lane >> 3) & 1) * 8;
    const int lcol = (lane >> 4) * 8;
    const uint32_t laneoff = (uint32_t)(lrow * (LDT * 2) + lcol * 2);

    const int wm = (wid & 1) * 64;
    const int wn = (wid >> 1) * 32;

    float acc[4][4][4];
#pragma unroll
    for (int i = 0; i < 4; i++)
#pragma unroll
        for (int j = 0; j < 4; j++)
#pragma unroll
            for (int e = 0; e < 4; e++) acc[i][j][e] = 0.0f;

#pragma unroll
    for (int arr = 0; arr < 4; arr++)
#pragma unroll
        for (int h = 0; h < 2; h++) {
            const int c = tid + h * 256;
            const int row = c >> 2, c4 = c & 3;
            cp16(sb + arr * TBY + row * (LDT * 2) + c4 * 16,
                 gp[arr] + (size_t)(gbase[arr] + row) * EMB + c4 * 8);
        }
    cp_commit();

    const int NKC = EMB / 32;
    for (int kc = 0; kc < NKC; kc++) {
        const int buf = kc & 1;
        if (kc + 1 < NKC) {
            const uint32_t so = sb + (buf ^ 1) * BUFB;
            const int koff = (kc + 1) * 32;
#pragma unroll
            for (int arr = 0; arr < 4; arr++)
#pragma unroll
                for (int h = 0; h < 2; h++) {
                    const int c = tid + h * 256;
                    const int row = c >> 2, c4 = c & 3;
                    cp16(so + arr * TBY + row * (LDT * 2) + c4 * 16,
                         gp[arr] + (size_t)(gbase[arr] + row) * EMB + koff + c4 * 8);
                }
            cp_commit();
            cp_wait<1>();
        } else {
            cp_wait<0>();
        }
        __syncthreads();

        const uint32_t tb = sb + buf * BUFB;
#pragma unroll
        for (int ks = 0; ks < 32; ks += 16) {
            uint32_t ah[4][4], al[4][4];
#pragma unroll
            for (int i = 0; i < 4; i++) {
                const uint32_t ao = tb + (wm + i * 16) * (LDT * 2) + ks * 2 + laneoff;
                ldsm_x4(ah[i], ao);
                ldsm_x4(al[i], ao + TBY);
            }
            uint32_t b0[4], b1[4];
            {
                const uint32_t bo = tb + 2 * TBY + wn * (LDT * 2) + ks * 2 + laneoff;
                ldsm_x4(b0, bo);
                ldsm_x4(b1, bo + 16 * (LDT * 2));
            }
#pragma unroll
            for (int i = 0; i < 4; i++) {
                mma_bf16(acc[i][0], ah[i], b0[0], b0[2]);
                mma_bf16(acc[i][1], ah[i], b0[1], b0[3]);
                mma_bf16(acc[i][2], ah[i], b1[0], b1[2]);
                mma_bf16(acc[i][3], ah[i], b1[1], b1[3]);
            }
#pragma unroll
            for (int i = 0; i < 4; i++) {
                mma_bf16(acc[i][0], al[i], b0[0], b0[2]);
                mma_bf16(acc[i][1], al[i], b0[1], b0[3]);
                mma_bf16(acc[i][2], al[i], b1[0], b1[2]);
                mma_bf16(acc[i][3], al[i], b1[1], b1[3]);
            }
            {
                const uint32_t bo = tb + 3 * TBY + wn * (LDT * 2) + ks * 2 + laneoff;
                ldsm_x4(b0, bo);
                ldsm_x4(b1, bo + 16 * (LDT * 2));
            }
#pragma unroll
            for (int i = 0; i < 4; i++) {
                mma_bf16(acc[i][0], ah[i], b0[0], b0[2]);
                mma_bf16(acc[i][1], ah[i], b0[1], b0[3]);
                mma_bf16(acc[i][2], ah[i], b1[0], b1[2]);
                mma_bf16(acc[i][3], ah[i], b1[1], b1[3]);
            }
        }
        __syncthreads();
    }

#pragma unroll
    for (int i = 0; i < 4; i++) {
        const int r = m0 + wm + i * 16 + (lane >> 2);
#pragma unroll
        for (int j = 0; j < 4; j++) {
            const int c = n0 + wn + j * 8 + (lane & 3) * 2;
            const float2 bv = *(const float2*)(bias + c);
            float o00 = (acc[i][j][0] + bv.x) * scale;
            float o01 = (acc[i][j][1] + bv.y) * scale;
            float o10 = (acc[i][j][2] + bv.x) * scale;
            float o11 = (acc[i][j][3] + bv.y) * scale;
            if (HOUT) {
                __half2 h0 = __floats2half2_rn(o00, o01);
                __half2 h1 = __floats2half2_rn(o10, o11);
                *(__half2*)(Ch + (size_t)r * EMB + c) = h0;
                *(__half2*)(Ch + (size_t)(r + 8) * EMB + c) = h1;
            } else {
                *(float2*)(Cf + (size_t)r * EMB + c) = make_float2(o00, o01);
                *(float2*)(Cf + (size_t)(r + 8) * EMB + c) = make_float2(o10, o11);
            }
        }
    }
}

// ---------------------------------------------------------------------------
// Flash attention, fp16 mma.sync (FA2-style).
// CTA: 128 q rows, 8 warps x 16 rows. 64-key tiles, cp.async double buffer.
// Q fragments register-resident; S accumulators reused in place as P.
// Output written directly as bf16 hi/lo splits for the O-projection GEMM.
// ---------------------------------------------------------------------------
#define ALD 72                      // fp16 row stride (144B, conflict-free)
#define AQR 128
#define AKT 64
#define KVB (AKT * ALD * 2)         // 9216 B per K/V buffer
#define ASM_Q   (AQR * ALD * 2)     // 18432
#define ASM_K   (ASM_Q)             // K at +18432, 2 bufs
#define ASM_V   (ASM_K + 2 * KVB)
#define ASM_MSK (ASM_V + 2 * KVB)   // 55296
#define ASM_TOT (ASM_MSK + 512)     // 55808

__global__ __launch_bounds__(256)
void attn_mma(const __half* __restrict__ Qh, const __half* __restrict__ Kh,
              const __half* __restrict__ Vh, const int* __restrict__ mask,
              __nv_bfloat16* __restrict__ Ohi, __nv_bfloat16* __restrict__ Olo)
{
    extern __shared__ char sma[];
    const uint32_t sb = smem_to_u32(sma);
    const int* mskp = (const int*)(sma + ASM_MSK);

    const int tid = threadIdx.x, wid = tid >> 5, lane = tid & 31;
    const int qb = blockIdx.x;
    const int n = blockIdx.y >> 4, h = blockIdx.y & 15;
    const int q0 = qb * AQR;

    const size_t qg  = ((size_t)(n * S_LEN + q0)) * EMB + h * HD;
    const size_t kvg = ((size_t)n * S_LEN) * EMB + h * HD;

    const int lrow = (lane & 7) + ((lane >> 3) & 1) * 8;
    const int lcol = (lane >> 4) * 8;
    const uint32_t laneoff = (uint32_t)(lrow * (ALD * 2) + lcol * 2);

    // prologue: Q tile + K/V/mask tile 0
#pragma unroll
    for (int i = 0; i < 4; i++) {
        const int c = tid + i * 256;           // 1024 chunks
        const int row = c >> 3, c4 = c & 7;
        cp16(sb + row * (ALD * 2) + c4 * 16, Qh + qg + (size_t)row * EMB + c4 * 8);
    }
#pragma unroll
    for (int i = 0; i < 2; i++) {
        const int c = tid + i * 256;           // 512 chunks
        const int row = c >> 3, c4 = c & 7;
        cp16(sb + ASM_K + row * (ALD * 2) + c4 * 16,
             Kh + kvg + (size_t)row * EMB + c4 * 8);
        cp16(sb + ASM_V + row * (ALD * 2) + c4 * 16,
             Vh + kvg + (size_t)row * EMB + c4 * 8);
    }
    if (tid < 16)
        cp16(sb + ASM_MSK + tid * 16, mask + n * S_LEN + tid * 4);
    cp_commit();

    uint32_t qa[4][4];
    float o[8][4];
#pragma unroll
    for (int j = 0; j < 8; j++)
#pragma unroll
        for (int e = 0; e < 4; e++) o[j][e] = 0.0f;
    float m0r = -1e30f, m1r = -1e30f, l0 = 0.0f, l1 = 0.0f;

    const int NIT = S_LEN / AKT;   // 32
    for (int kt = 0; kt < NIT; kt++) {
        const int buf = kt & 1;
        if (kt + 1 < NIT) {
            const size_t kvo = kvg + (size_t)(kt + 1) * AKT * EMB;
            const uint32_t kd = sb + ASM_K + (buf ^ 1) * KVB;
            const uint32_t vd = sb + ASM_V + (buf ^ 1) * KVB;
#pragma unroll
            for (int i = 0; i < 2; i++) {
                const int c = tid + i * 256;
                const int row = c >> 3, c4 = c & 7;
                cp16(kd + row * (ALD * 2) + c4 * 16, Kh + kvo + (size_t)row * EMB + c4 * 8);
                cp16(vd + row * (ALD * 2) + c4 * 16, Vh + kvo + (size_t)row * EMB + c4 * 8);
            }
            if (tid < 16)
                cp16(sb + ASM_MSK + (buf ^ 1) * 256 + tid * 16,
                     mask + n * S_LEN + (kt + 1) * AKT + tid * 4);
            cp_commit();
            cp_wait<1>();
        } else {
            cp_wait<0>();
        }
        __syncthreads();

        if (kt == 0) {
#pragma unroll
            for (int t = 0; t < 4; t++)
                ldsm_x4(qa[t], sb + (wid * 16) * (ALD * 2) + t * 32 + laneoff);
        }

        const uint32_t kb_ = sb + ASM_K + buf * KVB;
        const uint32_t vb_ = sb + ASM_V + buf * KVB;
        const int* mk = mskp + buf * 64;

        // S = Qs @ K^T  (Q pre-scaled by 1/32)
        float s[8][4];
#pragma unroll
        for (int j = 0; j < 8; j++)
#pragma unroll
            for (int e = 0; e < 4; e++) s[j][e] = 0.0f;
#pragma unroll
        for (int t = 0; t < 4; t++)
#pragma unroll
            for (int g = 0; g < 4; g++) {
                uint32_t kb[4];
                ldsm_x4(kb, kb_ + (g * 16) * (ALD * 2) + t * 32 + laneoff);
                mma_f16(s[2 * g],     qa[t], kb[0], kb[2]);
                mma_f16(s[2 * g + 1], qa[t], kb[1], kb[3]);
            }

        // mask (tile j covers keys j*8..j*8+7)
#pragma unroll
        for (int j = 0; j < 8; j++) {
            const int c = j * 8 + (lane & 3) * 2;
            if (mk[c] == 0)     { s[j][0] = -1e20f; s[j][2] = -1e20f; }
            if (mk[c + 1] == 0) { s[j][1] = -1e20f; s[j][3] = -1e20f; }
        }

        // online softmax (rows: r0 = lane>>2, r1 = r0+8; quad = same row)
        float mx0 = s[0][0], mx1 = s[0][2];
#pragma unroll
        for (int j = 0; j < 8; j++) {
            mx0 = fmaxf(mx0, fmaxf(s[j][0], s[j][1]));
            mx1 = fmaxf(mx1, fmaxf(s[j][2], s[j][3]));
        }
        mx0 = fmaxf(mx0, __shfl_xor_sync(0xffffffffu, mx0, 1));
        mx0 = fmaxf(mx0, __shfl_xor_sync(0xffffffffu, mx0, 2));
        mx1 = fmaxf(mx1, __shfl_xor_sync(0xffffffffu, mx1, 1));
        mx1 = fmaxf(mx1, __shfl_xor_sync(0xffffffffu, mx1, 2));
        const float mn0 = fmaxf(m0r, mx0), mn1 = fmaxf(m1r, mx1);
        const float c0 = __expf(m0r - mn0), c1 = __expf(m1r - mn1);
        m0r = mn0; m1r = mn1;
        l0 *= c0; l1 *= c1;
#pragma unroll
        for (int j = 0; j < 8; j++) {
            s[j][0] = __expf(s[j][0] - mn0);
            s[j][1] = __expf(s[j][1] - mn0);
            s[j][2] = __expf(s[j][2] - mn1);
            s[j][3] = __expf(s[j][3] - mn1);
            l0 += s[j][0] + s[j][1];
            l1 += s[j][2] + s[j][3];
            o[j][0] *= c0; o[j][1] *= c0;
            o[j][2] *= c1; o[j][3] *= c1;
        }

        // O += P @ V  (S regs reused as P A-fragments)
#pragma unroll
        for (int t = 0; t < 4; t++) {
            uint32_t pa[4];
            pa[0] = packh2(s[2 * t][0],     s[2 * t][1]);
            pa[1] = packh2(s[2 * t][2],     s[2 * t][3]);
            pa[2] = packh2(s[2 * t + 1][0], s[2 * t + 1][1]);
            pa[3] = packh2(s[2 * t + 1][2], s[2 * t + 1][3]);
#pragma unroll
            for (int jd = 0; jd < 4; jd++) {
                uint32_t vb[4];
                ldsm_x4_t(vb, vb_ + (t * 16 + lrow) * (ALD * 2)
                              + (jd * 16 + lcol) * 2);
                mma_f16(o[2 * jd],     pa, vb[0], vb[1]);
                mma_f16(o[2 * jd + 1], pa, vb[2], vb[3]);
            }
        }
        __syncthreads();
    }

    // epilogue: finish row sums, normalize, write bf16 hi/lo splits
    l0 += __shfl_xor_sync(0xffffffffu, l0, 1);
    l0 += __shfl_xor_sync(0xffffffffu, l0, 2);
    l1 += __shfl_xor_sync(0xffffffffu, l1, 1);
    l1 += __shfl_xor_sync(0xffffffffu, l1, 2);
    const float i0 = 1.0f / l0, i1 = 1.0f / l1;

    const int r0 = q0 + wid * 16 + (lane >> 2);
#pragma unroll
    for (int j = 0; j < 8; j++) {
        const int d = h * HD + j * 8 + (lane & 3) * 2;
        const size_t off0 = (size_t)(n * S_LEN + r0) * EMB + d;
        const size_t off1 = off0 + 8 * EMB;
        float v0 = o[j][0] * i0, v1 = o[j][1] * i0;
        float v2 = o[j][2] * i1, v3 = o[j][3] * i1;
        __nv_bfloat162 h2, l2;
        h2.x = __float2bfloat16_rn(v0);
        h2.y = __float2bfloat16_rn(v1);
        l2.x = __float2bfloat16_rn(v0 - __bfloat162float(h2.x));
        l2.y = __float2bfloat16_rn(v1 - __bfloat162float(h2.y));
        *(__nv_bfloat162*)(Ohi + off0) = h2;
        *(__nv_bfloat162*)(Olo + off0) = l2;
        h2.x = __float2bfloat16_rn(v2);
        h2.y = __float2bfloat16_rn(v3);
        l2.x = __float2bfloat16_rn(v2 - __bfloat162float(h2.x));
        l2.y = __float2bfloat16_rn(v3 - __bfloat162float(h2.y));
        *(__nv_bfloat162*)(Ohi + off1) = h2;
        *(__nv_bfloat162*)(Olo + off1) = l2;
    }
}

// ---------------------------------------------------------------------------
extern "C" void kernel_launch(void* const* d_in, const int* in_sizes, int n_in,
                              void* d_out, int out_size)
{
    const float* values = (const float*)d_in[0];
    const float* keys   = (const float*)d_in[1];
    const float* query  = (const float*)d_in[2];
    const int*   mask   = (const int*)  d_in[3];
    const float* Wv = (const float*)d_in[4];
    const float* bv = (const float*)d_in[5];
    const float* Wk = (const float*)d_in[6];
    const float* bk = (const float*)d_in[7];
    const float* Wq = (const float*)d_in[8];
    const float* bq = (const float*)d_in[9];
    const float* Wo = (const float*)d_in[10];
    const float* bo = (const float*)d_in[11];
    float* out = (float*)d_out;

    __nv_bfloat16 *wth, *wtl, *ahi, *alo;
    __half *qh, *kh, *vh;
    cudaGetSymbolAddress((void**)&wth, g_wt_hi);
    cudaGetSymbolAddress((void**)&wtl, g_wt_lo);
    cudaGetSymbolAddress((void**)&ahi, g_a_hi);
    cudaGetSymbolAddress((void**)&alo, g_a_lo);
    cudaGetSymbolAddress((void**)&qh,  g_qh);
    cudaGetSymbolAddress((void**)&kh,  g_kh);
    cudaGetSymbolAddress((void**)&vh,  g_vh);

    const int gemm_smem = 2 * BUFB;   // 81920 B
    cudaFuncSetAttribute(gemm_ms<true>,
                         cudaFuncAttributeMaxDynamicSharedMemorySize, gemm_smem);
    cudaFuncSetAttribute(gemm_ms<false>,
                         cudaFuncAttributeMaxDynamicSharedMemorySize, gemm_smem);
    cudaFuncSetAttribute(attn_mma,
                         cudaFuncAttributeMaxDynamicSharedMemorySize, ASM_TOT);

    const size_t WSZ = (size_t)EMB * EMB;
    const int M = NBATCH * S_LEN;
    dim3 tgrid(32, 32), tblk(32, 8);
    transpose_split<<<tgrid, tblk>>>(Wq, wth + 0 * WSZ, wtl + 0 * WSZ);
    transpose_split<<<tgrid, tblk>>>(Wk, wth + 1 * WSZ, wtl + 1 * WSZ);
    transpose_split<<<tgrid, tblk>>>(Wv, wth + 2 * WSZ, wtl + 2 * WSZ);
    transpose_split<<<tgrid, tblk>>>(Wo, wth + 3 * WSZ, wtl + 3 * WSZ);

    const int splitg = (M * EMB / 4) / 256;
    dim3 ggrid(EMB / 128, M / 128);

    split2<<<splitg, 256>>>(query, ahi, alo);
    gemm_ms<true><<<ggrid, 256, gemm_smem>>>(ahi, alo, wth + 0 * WSZ, wtl + 0 * WSZ,
                                             bq, 0.03125f, nullptr, qh);
    split2<<<splitg, 256>>>(keys, ahi, alo);
    gemm_ms<true><<<ggrid, 256, gemm_smem>>>(ahi, alo, wth + 1 * WSZ, wtl + 1 * WSZ,
                                             bk, 1.0f, nullptr, kh);
    split2<<<splitg, 256>>>(values, ahi, alo);
    gemm_ms<true><<<ggrid, 256, gemm_smem>>>(ahi, alo, wth + 2 * WSZ, wtl + 2 * WSZ,
                                             bv, 1.0f, nullptr, vh);

    dim3 agrid(S_LEN / AQR, NBATCH * NH);   // (16, 64)
    attn_mma<<<agrid, 256, ASM_TOT>>>(qh, kh, vh, mask, ahi, alo);

    gemm_ms<false><<<ggrid, 256, gemm_smem>>>(ahi, alo, wth + 3 * WSZ, wtl + 3 * WSZ,
                                              bo, 1.0f, out, nullptr);
}

// round 8
// speedup vs baseline: 3.6069x; 1.3275x over previous
#include <cuda_runtime.h>
#include <cuda_fp16.h>
#include <cstdint>

#define S_LEN 2048
#define NBATCH 4
#define EMB 1024
#define NH 16
#define HD 64
#define MSZ (NBATCH * S_LEN * EMB)

// ---------------------------------------------------------------------------
// Scratch (allocation-free rule: __device__ globals)
// ---------------------------------------------------------------------------
__device__ __half g_wt[4 * EMB * EMB];     // W^T fp16 [4][N][K]
__device__ __half g_ah[3][MSZ];            // activation split high (q,k,v inputs / O)
__device__ __half g_al[3][MSZ];            // activation split low
__device__ __half g_qh[MSZ];               // q (pre-scaled 1/32) fp16
__device__ __half g_kh[MSZ];               // k fp16
__device__ __half g_vh[MSZ];               // v fp16

// ---------------------------------------------------------------------------
// Base-ISA PTX helpers (harness PTX target is plain sm_103 — no tcgen05)
// ---------------------------------------------------------------------------
__device__ __forceinline__ uint32_t smem_to_u32(const void* p) {
    uint32_t a;
    asm("{ .reg .u64 t; cvta.to.shared.u64 t, %1; cvt.u32.u64 %0, t; }"
        : "=r"(a) : "l"(p));
    return a;
}

__device__ __forceinline__ void ldsm_x4(uint32_t* r, uint32_t addr) {
    asm volatile("ldmatrix.sync.aligned.m8n8.x4.shared.b16 {%0,%1,%2,%3}, [%4];"
                 : "=r"(r[0]), "=r"(r[1]), "=r"(r[2]), "=r"(r[3]) : "r"(addr));
}
__device__ __forceinline__ void ldsm_x4_t(uint32_t* r, uint32_t addr) {
    asm volatile("ldmatrix.sync.aligned.m8n8.x4.trans.shared.b16 {%0,%1,%2,%3}, [%4];"
                 : "=r"(r[0]), "=r"(r[1]), "=r"(r[2]), "=r"(r[3]) : "r"(addr));
}

__device__ __forceinline__ void mma_f16(float* d, const uint32_t* a,
                                        uint32_t b0, uint32_t b1) {
    asm volatile(
        "mma.sync.aligned.m16n8k16.row.col.f32.f16.f16.f32 "
        "{%0,%1,%2,%3}, {%4,%5,%6,%7}, {%8,%9}, {%0,%1,%2,%3};"
        : "+f"(d[0]), "+f"(d[1]), "+f"(d[2]), "+f"(d[3])
        : "r"(a[0]), "r"(a[1]), "r"(a[2]), "r"(a[3]), "r"(b0), "r"(b1));
}

__device__ __forceinline__ void cp16(uint32_t s, const void* g) {
    asm volatile("cp.async.cg.shared.global [%0], [%1], 16;" :: "r"(s), "l"(g));
}
__device__ __forceinline__ void cp_commit() {
    asm volatile("cp.async.commit_group;" ::: "memory");
}
template <int N>
__device__ __forceinline__ void cp_wait() {
    asm volatile("cp.async.wait_group %0;" :: "n"(N) : "memory");
}

__device__ __forceinline__ uint32_t packh2(float a, float b) {
    __half2 h = __floats2half2_rn(a, b);
    return *(uint32_t*)&h;
}

// ---------------------------------------------------------------------------
// Weight transpose: W[K][N] fp32 -> Wt[N][K] fp16
// ---------------------------------------------------------------------------
__global__ void transpose_half(const float* __restrict__ W,
                               __half* __restrict__ T)
{
    __shared__ float t[32][33];
    const int tx = threadIdx.x, ty = threadIdx.y;
    const int bx = blockIdx.x * 32, by = blockIdx.y * 32;
#pragma unroll
    for (int j = 0; j < 4; j++)
        t[ty + j * 8][tx] = W[(size_t)(by + ty + j * 8) * EMB + bx + tx];
    __syncthreads();
#pragma unroll
    for (int j = 0; j < 4; j++) {
        float v = t[tx][ty + j * 8];
        T[(size_t)(bx + ty + j * 8) * EMB + by + tx] = __float2half_rn(v);
    }
}

// ---------------------------------------------------------------------------
// Activation split: X fp32 -> hi/lo fp16 (elementwise)
// ---------------------------------------------------------------------------
union H4 { __half h[4]; uint2 u; };

__global__ __launch_bounds__(256)
void split2h(const float* __restrict__ X, __half* __restrict__ H,
             __half* __restrict__ L)
{
    const int i = blockIdx.x * 256 + threadIdx.x;
    float4 v = ((const float4*)X)[i];
    float f[4] = {v.x, v.y, v.z, v.w};
    H4 h, l;
#pragma unroll
    for (int j = 0; j < 4; j++) {
        h.h[j] = __float2half_rn(f[j]);
        l.h[j] = __float2half_rn(f[j] - __half2float(h.h[j]));
    }
    ((uint2*)H)[i] = h.u;
    ((uint2*)L)[i] = l.u;
}

// ---------------------------------------------------------------------------
// mma.sync fp16 GEMM, A split hi/lo (2 products): C = A @ W^T + bias
// 128x128 block, BK=32, 8 warps, cp.async double buffer, grid.z selects input.
// ---------------------------------------------------------------------------
#define LDT 40
#define TBY (128 * LDT * 2)          // 10240 B per tile
#define BUFB (3 * TBY)               // Ahi|Alo|B per buffer

struct GArgs {
    const __half* Ahi[3];
    const __half* Alo[3];
    const __half* B[3];
    const float*  bias[3];
    float         scale[3];
    __half*       Ch[3];
    float*        Cf;
};

template <bool HOUT>
__global__ __launch_bounds__(256, 2)
void gemm_ms(GArgs args)
{
    extern __shared__ char smc[];
    const uint32_t sb = smem_to_u32(smc);
    const int tid = threadIdx.x;
    const int wid = tid >> 5, lane = tid & 31;
    const int m0 = blockIdx.y * 128, n0 = blockIdx.x * 128;
    const int z = blockIdx.z;

    const __half* gp[3] = {args.Ahi[z], args.Alo[z], args.B[z]};
    const int gbase[3] = {m0, m0, n0};

    const int lrow = (lane & 7) + ((lane >> 3) & 1) * 8;
    const int lcol = (lane >> 4) * 8;
    const uint32_t laneoff = (uint32_t)(lrow * (LDT * 2) + lcol * 2);

    const int wm = (wid & 1) * 64;
    const int wn = (wid >> 1) * 32;

    float acc[4][4][4];
#pragma unroll
    for (int i = 0; i < 4; i++)
#pragma unroll
        for (int j = 0; j < 4; j++)
#pragma unroll
            for (int e = 0; e < 4; e++) acc[i][j][e] = 0.0f;

#pragma unroll
    for (int arr = 0; arr < 3; arr++)
#pragma unroll
        for (int h = 0; h < 2; h++) {
            const int c = tid + h * 256;
            const int row = c >> 2, c4 = c & 3;
            cp16(sb + arr * TBY + row * (LDT * 2) + c4 * 16,
                 gp[arr] + (size_t)(gbase[arr] + row) * EMB + c4 * 8);
        }
    cp_commit();

    const int NKC = EMB / 32;
    for (int kc = 0; kc < NKC; kc++) {
        const int buf = kc & 1;
        if (kc + 1 < NKC) {
            const uint32_t so = sb + (buf ^ 1) * BUFB;
            const int koff = (kc + 1) * 32;
#pragma unroll
            for (int arr = 0; arr < 3; arr++)
#pragma unroll
                for (int h = 0; h < 2; h++) {
                    const int c = tid + h * 256;
                    const int row = c >> 2, c4 = c & 3;
                    cp16(so + arr * TBY + row * (LDT * 2) + c4 * 16,
                         gp[arr] + (size_t)(gbase[arr] + row) * EMB + koff + c4 * 8);
                }
            cp_commit();
            cp_wait<1>();
        } else {
            cp_wait<0>();
        }
        __syncthreads();

        const uint32_t tb = sb + buf * BUFB;
#pragma unroll
        for (int ks = 0; ks < 32; ks += 16) {
            uint32_t ah[4][4], al[4][4];
#pragma unroll
            for (int i = 0; i < 4; i++) {
                const uint32_t ao = tb + (wm + i * 16) * (LDT * 2) + ks * 2 + laneoff;
                ldsm_x4(ah[i], ao);
                ldsm_x4(al[i], ao + TBY);
            }
            uint32_t b0[4], b1[4];
            {
                const uint32_t bo = tb + 2 * TBY + wn * (LDT * 2) + ks * 2 + laneoff;
                ldsm_x4(b0, bo);
                ldsm_x4(b1, bo + 16 * (LDT * 2));
            }
#pragma unroll
            for (int i = 0; i < 4; i++) {
                mma_f16(acc[i][0], ah[i], b0[0], b0[2]);
                mma_f16(acc[i][1], ah[i], b0[1], b0[3]);
                mma_f16(acc[i][2], ah[i], b1[0], b1[2]);
                mma_f16(acc[i][3], ah[i], b1[1], b1[3]);
            }
#pragma unroll
            for (int i = 0; i < 4; i++) {
                mma_f16(acc[i][0], al[i], b0[0], b0[2]);
                mma_f16(acc[i][1], al[i], b0[1], b0[3]);
                mma_f16(acc[i][2], al[i], b1[0], b1[2]);
                mma_f16(acc[i][3], al[i], b1[1], b1[3]);
            }
        }
        __syncthreads();
    }

    const float scale = args.scale[z];
    const float* bias = args.bias[z];
#pragma unroll
    for (int i = 0; i < 4; i++) {
        const int r = m0 + wm + i * 16 + (lane >> 2);
#pragma unroll
        for (int j = 0; j < 4; j++) {
            const int c = n0 + wn + j * 8 + (lane & 3) * 2;
            const float2 bv = *(const float2*)(bias + c);
            float o00 = (acc[i][j][0] + bv.x) * scale;
            float o01 = (acc[i][j][1] + bv.y) * scale;
            float o10 = (acc[i][j][2] + bv.x) * scale;
            float o11 = (acc[i][j][3] + bv.y) * scale;
            if (HOUT) {
                __half* Ch = args.Ch[z];
                *(__half2*)(Ch + (size_t)r * EMB + c) = __floats2half2_rn(o00, o01);
                *(__half2*)(Ch + (size_t)(r + 8) * EMB + c) = __floats2half2_rn(o10, o11);
            } else {
                *(float2*)(args.Cf + (size_t)r * EMB + c) = make_float2(o00, o01);
                *(float2*)(args.Cf + (size_t)(r + 8) * EMB + c) = make_float2(o10, o11);
            }
        }
    }
}

// ---------------------------------------------------------------------------
// Flash attention, fp16 mma.sync (FA2-style).
// CTA: 128 q rows, 8 warps x 16 rows. 64-key tiles, cp.async double buffer.
// Output written directly as fp16 hi/lo splits for the O-projection GEMM.
// ---------------------------------------------------------------------------
#define ALD 72
#define AQR 128
#define AKT 64
#define KVB (AKT * ALD * 2)
#define ASM_Q   (AQR * ALD * 2)
#define ASM_K   (ASM_Q)
#define ASM_V   (ASM_K + 2 * KVB)
#define ASM_MSK (ASM_V + 2 * KVB)
#define ASM_TOT (ASM_MSK + 512)

__global__ __launch_bounds__(256)
void attn_mma(const __half* __restrict__ Qh, const __half* __restrict__ Kh,
              const __half* __restrict__ Vh, const int* __restrict__ mask,
              __half* __restrict__ Ohi, __half* __restrict__ Olo)
{
    extern __shared__ char sma[];
    const uint32_t sb = smem_to_u32(sma);
    const int* mskp = (const int*)(sma + ASM_MSK);

    const int tid = threadIdx.x, wid = tid >> 5, lane = tid & 31;
    const int qb = blockIdx.x;
    const int n = blockIdx.y >> 4, h = blockIdx.y & 15;
    const int q0 = qb * AQR;

    const size_t qg  = ((size_t)(n * S_LEN + q0)) * EMB + h * HD;
    const size_t kvg = ((size_t)n * S_LEN) * EMB + h * HD;

    const int lrow = (lane & 7) + ((lane >> 3) & 1) * 8;
    const int lcol = (lane >> 4) * 8;
    const uint32_t laneoff = (uint32_t)(lrow * (ALD * 2) + lcol * 2);

#pragma unroll
    for (int i = 0; i < 4; i++) {
        const int c = tid + i * 256;
        const int row = c >> 3, c4 = c & 7;
        cp16(sb + row * (ALD * 2) + c4 * 16, Qh + qg + (size_t)row * EMB + c4 * 8);
    }
#pragma unroll
    for (int i = 0; i < 2; i++) {
        const int c = tid + i * 256;
        const int row = c >> 3, c4 = c & 7;
        cp16(sb + ASM_K + row * (ALD * 2) + c4 * 16,
             Kh + kvg + (size_t)row * EMB + c4 * 8);
        cp16(sb + ASM_V + row * (ALD * 2) + c4 * 16,
             Vh + kvg + (size_t)row * EMB + c4 * 8);
    }
    if (tid < 16)
        cp16(sb + ASM_MSK + tid * 16, mask + n * S_LEN + tid * 4);
    cp_commit();

    uint32_t qa[4][4];
    float o[8][4];
#pragma unroll
    for (int j = 0; j < 8; j++)
#pragma unroll
        for (int e = 0; e < 4; e++) o[j][e] = 0.0f;
    float m0r = -1e30f, m1r = -1e30f, l0 = 0.0f, l1 = 0.0f;

    const int NIT = S_LEN / AKT;
    for (int kt = 0; kt < NIT; kt++) {
        const int buf = kt & 1;
        if (kt + 1 < NIT) {
            const size_t kvo = kvg + (size_t)(kt + 1) * AKT * EMB;
            const uint32_t kd = sb + ASM_K + (buf ^ 1) * KVB;
            const uint32_t vd = sb + ASM_V + (buf ^ 1) * KVB;
#pragma unroll
            for (int i = 0; i < 2; i++) {
                const int c = tid + i * 256;
                const int row = c >> 3, c4 = c & 7;
                cp16(kd + row * (ALD * 2) + c4 * 16, Kh + kvo + (size_t)row * EMB + c4 * 8);
                cp16(vd + row * (ALD * 2) + c4 * 16, Vh + kvo + (size_t)row * EMB + c4 * 8);
            }
            if (tid < 16)
                cp16(sb + ASM_MSK + (buf ^ 1) * 256 + tid * 16,
                     mask + n * S_LEN + (kt + 1) * AKT + tid * 4);
            cp_commit();
            cp_wait<1>();
        } else {
            cp_wait<0>();
        }
        __syncthreads();

        if (kt == 0) {
#pragma unroll
            for (int t = 0; t < 4; t++)
                ldsm_x4(qa[t], sb + (wid * 16) * (ALD * 2) + t * 32 + laneoff);
        }

        const uint32_t kb_ = sb + ASM_K + buf * KVB;
        const uint32_t vb_ = sb + ASM_V + buf * KVB;
        const int* mk = mskp + buf * 64;

        float s[8][4];
#pragma unroll
        for (int j = 0; j < 8; j++)
#pragma unroll
            for (int e = 0; e < 4; e++) s[j][e] = 0.0f;
#pragma unroll
        for (int t = 0; t < 4; t++)
#pragma unroll
            for (int g = 0; g < 4; g++) {
                uint32_t kb[4];
                ldsm_x4(kb, kb_ + (g * 16) * (ALD * 2) + t * 32 + laneoff);
                mma_f16(s[2 * g],     qa[t], kb[0], kb[2]);
                mma_f16(s[2 * g + 1], qa[t], kb[1], kb[3]);
            }

#pragma unroll
        for (int j = 0; j < 8; j++) {
            const int c = j * 8 + (lane & 3) * 2;
            if (mk[c] == 0)     { s[j][0] = -1e20f; s[j][2] = -1e20f; }
            if (mk[c + 1] == 0) { s[j][1] = -1e20f; s[j][3] = -1e20f; }
        }

        float mx0 = s[0][0], mx1 = s[0][2];
#pragma unroll
        for (int j = 0; j < 8; j++) {
            mx0 = fmaxf(mx0, fmaxf(s[j][0], s[j][1]));
            mx1 = fmaxf(mx1, fmaxf(s[j][2], s[j][3]));
        }
        mx0 = fmaxf(mx0, __shfl_xor_sync(0xffffffffu, mx0, 1));
        mx0 = fmaxf(mx0, __shfl_xor_sync(0xffffffffu, mx0, 2));
        mx1 = fmaxf(mx1, __shfl_xor_sync(0xffffffffu, mx1, 1));
        mx1 = fmaxf(mx1, __shfl_xor_sync(0xffffffffu, mx1, 2));
        const float mn0 = fmaxf(m0r, mx0), mn1 = fmaxf(m1r, mx1);
        const float c0 = __expf(m0r - mn0), c1 = __expf(m1r - mn1);
        m0r = mn0; m1r = mn1;
        l0 *= c0; l1 *= c1;
#pragma unroll
        for (int j = 0; j < 8; j++) {
            s[j][0] = __expf(s[j][0] - mn0);
            s[j][1] = __expf(s[j][1] - mn0);
            s[j][2] = __expf(s[j][2] - mn1);
            s[j][3] = __expf(s[j][3] - mn1);
            l0 += s[j][0] + s[j][1];
            l1 += s[j][2] + s[j][3];
            o[j][0] *= c0; o[j][1] *= c0;
            o[j][2] *= c1; o[j][3] *= c1;
        }

#pragma unroll
        for (int t = 0; t < 4; t++) {
            uint32_t pa[4];
            pa[0] = packh2(s[2 * t][0],     s[2 * t][1]);
            pa[1] = packh2(s[2 * t][2],     s[2 * t][3]);
            pa[2] = packh2(s[2 * t + 1][0], s[2 * t + 1][1]);
            pa[3] = packh2(s[2 * t + 1][2], s[2 * t + 1][3]);
#pragma unroll
            for (int jd = 0; jd < 4; jd++) {
                uint32_t vb[4];
                ldsm_x4_t(vb, vb_ + (t * 16 + lrow) * (ALD * 2)
                              + (jd * 16 + lcol) * 2);
                mma_f16(o[2 * jd],     pa, vb[0], vb[1]);
                mma_f16(o[2 * jd + 1], pa, vb[2], vb[3]);
            }
        }
        __syncthreads();
    }

    l0 += __shfl_xor_sync(0xffffffffu, l0, 1);
    l0 += __shfl_xor_sync(0xffffffffu, l0, 2);
    l1 += __shfl_xor_sync(0xffffffffu, l1, 1);
    l1 += __shfl_xor_sync(0xffffffffu, l1, 2);
    const float i0 = 1.0f / l0, i1 = 1.0f / l1;

    const int r0 = q0 + wid * 16 + (lane >> 2);
#pragma unroll
    for (int j = 0; j < 8; j++) {
        const int d = h * HD + j * 8 + (lane & 3) * 2;
        const size_t off0 = (size_t)(n * S_LEN + r0) * EMB + d;
        const size_t off1 = off0 + 8 * EMB;
        float v0 = o[j][0] * i0, v1 = o[j][1] * i0;
        float v2 = o[j][2] * i1, v3 = o[j][3] * i1;
        __half2 h2, l2;
        h2.x = __float2half_rn(v0);
        h2.y = __float2half_rn(v1);
        l2.x = __float2half_rn(v0 - __half2float(h2.x));
        l2.y = __float2half_rn(v1 - __half2float(h2.y));
        *(__half2*)(Ohi + off0) = h2;
        *(__half2*)(Olo + off0) = l2;
        h2.x = __float2half_rn(v2);
        h2.y = __float2half_rn(v3);
        l2.x = __float2half_rn(v2 - __half2float(h2.x));
        l2.y = __float2half_rn(v3 - __half2float(h2.y));
        *(__half2*)(Ohi + off1) = h2;
        *(__half2*)(Olo + off1) = l2;
    }
}

// ---------------------------------------------------------------------------
extern "C" void kernel_launch(void* const* d_in, const int* in_sizes, int n_in,
                              void* d_out, int out_size)
{
    const float* values = (const float*)d_in[0];
    const float* keys   = (const float*)d_in[1];
    const float* query  = (const float*)d_in[2];
    const int*   mask   = (const int*)  d_in[3];
    const float* Wv = (const float*)d_in[4];
    const float* bv = (const float*)d_in[5];
    const float* Wk = (const float*)d_in[6];
    const float* bk = (const float*)d_in[7];
    const float* Wq = (const float*)d_in[8];
    const float* bq = (const float*)d_in[9];
    const float* Wo = (const float*)d_in[10];
    const float* bo = (const float*)d_in[11];
    float* out = (float*)d_out;

    __half *wt, *ah, *al, *qh, *kh, *vh;
    cudaGetSymbolAddress((void**)&wt, g_wt);
    cudaGetSymbolAddress((void**)&ah, g_ah);
    cudaGetSymbolAddress((void**)&al, g_al);
    cudaGetSymbolAddress((void**)&qh, g_qh);
    cudaGetSymbolAddress((void**)&kh, g_kh);
    cudaGetSymbolAddress((void**)&vh, g_vh);

    const int gemm_smem = 2 * BUFB;   // 61440 B
    cudaFuncSetAttribute(gemm_ms<true>,
                         cudaFuncAttributeMaxDynamicSharedMemorySize, gemm_smem);
    cudaFuncSetAttribute(gemm_ms<false>,
                         cudaFuncAttributeMaxDynamicSharedMemorySize, gemm_smem);
    cudaFuncSetAttribute(attn_mma,
                         cudaFuncAttributeMaxDynamicSharedMemorySize, ASM_TOT);

    const size_t WSZ = (size_t)EMB * EMB;
    const int M = NBATCH * S_LEN;
    dim3 tgrid(32, 32), tblk(32, 8);
    transpose_half<<<tgrid, tblk>>>(Wq, wt + 0 * WSZ);
    transpose_half<<<tgrid, tblk>>>(Wk, wt + 1 * WSZ);
    transpose_half<<<tgrid, tblk>>>(Wv, wt + 2 * WSZ);
    transpose_half<<<tgrid, tblk>>>(Wo, wt + 3 * WSZ);

    const int splitg = (M * EMB / 4) / 256;
    split2h<<<splitg, 256>>>(query,  ah + 0 * MSZ, al + 0 * MSZ);
    split2h<<<splitg, 256>>>(keys,   ah + 1 * MSZ, al + 1 * MSZ);
    split2h<<<splitg, 256>>>(values, ah + 2 * MSZ, al + 2 * MSZ);

    // merged QKV GEMM: grid.z selects (input, weight, bias, scale, dest)
    GArgs qkv;
    qkv.Ahi[0] = ah + 0 * MSZ; qkv.Alo[0] = al + 0 * MSZ;
    qkv.Ahi[1] = ah + 1 * MSZ; qkv.Alo[1] = al + 1 * MSZ;
    qkv.Ahi[2] = ah + 2 * MSZ; qkv.Alo[2] = al + 2 * MSZ;
    qkv.B[0] = wt + 0 * WSZ; qkv.B[1] = wt + 1 * WSZ; qkv.B[2] = wt + 2 * WSZ;
    qkv.bias[0] = bq; qkv.bias[1] = bk; qkv.bias[2] = bv;
    qkv.scale[0] = 0.03125f; qkv.scale[1] = 1.0f; qkv.scale[2] = 1.0f;
    qkv.Ch[0] = qh; qkv.Ch[1] = kh; qkv.Ch[2] = vh;
    qkv.Cf = nullptr;
    dim3 qkvgrid(EMB / 128, M / 128, 3);
    gemm_ms<true><<<qkvgrid, 256, gemm_smem>>>(qkv);

    dim3 agrid(S_LEN / AQR, NBATCH * NH);
    attn_mma<<<agrid, 256, ASM_TOT>>>(qh, kh, vh, mask,
                                      ah + 0 * MSZ, al + 0 * MSZ);

    GArgs oproj;
    oproj.Ahi[0] = ah + 0 * MSZ; oproj.Alo[0] = al + 0 * MSZ;
    oproj.Ahi[1] = nullptr; oproj.Alo[1] = nullptr;
    oproj.Ahi[2] = nullptr; oproj.Alo[2] = nullptr;
    oproj.B[0] = wt + 3 * WSZ; oproj.B[1] = nullptr; oproj.B[2] = nullptr;
    oproj.bias[0] = bo; oproj.bias[1] = nullptr; oproj.bias[2] = nullptr;
    oproj.scale[0] = 1.0f; oproj.scale[1] = 1.0f; oproj.scale[2] = 1.0f;
    oproj.Ch[0] = nullptr; oproj.Ch[1] = nullptr; oproj.Ch[2] = nullptr;
    oproj.Cf = out;
    dim3 ogrid(EMB / 128, M / 128, 1);
    gemm_ms<false><<<ogrid, 256, gemm_smem>>>(oproj);
}

// round 9
// speedup vs baseline: 4.7336x; 1.3124x over previous
#include <cuda_runtime.h>
#include <cuda_fp16.h>
#include <cstdint>

#define S_LEN 2048
#define NBATCH 4
#define EMB 1024
#define NH 16
#define HD 64
#define MSZ (NBATCH * S_LEN * EMB)

// ---------------------------------------------------------------------------
// Scratch (allocation-free rule: __device__ globals)
// ---------------------------------------------------------------------------
__device__ __half g_wt[4 * EMB * EMB];     // W^T fp16 [4][N][K]
__device__ __half g_x[3][MSZ];             // fp16 casts of query/keys/values; [0] reused for attn out
__device__ __half g_qh[MSZ];               // q (pre-scaled 1/32) fp16
__device__ __half g_kh[MSZ];               // k fp16
__device__ __half g_vh[MSZ];               // v fp16

// ---------------------------------------------------------------------------
// Base-ISA PTX helpers (harness PTX target is plain sm_103 — no tcgen05)
// ---------------------------------------------------------------------------
__device__ __forceinline__ uint32_t smem_to_u32(const void* p) {
    uint32_t a;
    asm("{ .reg .u64 t; cvta.to.shared.u64 t, %1; cvt.u32.u64 %0, t; }"
        : "=r"(a) : "l"(p));
    return a;
}

__device__ __forceinline__ void ldsm_x4(uint32_t* r, uint32_t addr) {
    asm volatile("ldmatrix.sync.aligned.m8n8.x4.shared.b16 {%0,%1,%2,%3}, [%4];"
                 : "=r"(r[0]), "=r"(r[1]), "=r"(r[2]), "=r"(r[3]) : "r"(addr));
}
__device__ __forceinline__ void ldsm_x4_t(uint32_t* r, uint32_t addr) {
    asm volatile("ldmatrix.sync.aligned.m8n8.x4.trans.shared.b16 {%0,%1,%2,%3}, [%4];"
                 : "=r"(r[0]), "=r"(r[1]), "=r"(r[2]), "=r"(r[3]) : "r"(addr));
}

__device__ __forceinline__ void mma_f16(float* d, const uint32_t* a,
                                        uint32_t b0, uint32_t b1) {
    asm volatile(
        "mma.sync.aligned.m16n8k16.row.col.f32.f16.f16.f32 "
        "{%0,%1,%2,%3}, {%4,%5,%6,%7}, {%8,%9}, {%0,%1,%2,%3};"
        : "+f"(d[0]), "+f"(d[1]), "+f"(d[2]), "+f"(d[3])
        : "r"(a[0]), "r"(a[1]), "r"(a[2]), "r"(a[3]), "r"(b0), "r"(b1));
}

__device__ __forceinline__ void cp16(uint32_t s, const void* g) {
    asm volatile("cp.async.cg.shared.global [%0], [%1], 16;" :: "r"(s), "l"(g));
}
__device__ __forceinline__ void cp_commit() {
    asm volatile("cp.async.commit_group;" ::: "memory");
}
template <int N>
__device__ __forceinline__ void cp_wait() {
    asm volatile("cp.async.wait_group %0;" :: "n"(N) : "memory");
}

__device__ __forceinline__ uint32_t packh2(float a, float b) {
    __half2 h = __floats2half2_rn(a, b);
    return *(uint32_t*)&h;
}

// ---------------------------------------------------------------------------
// Merged weight transpose: 4x W[K][N] fp32 -> Wt[N][K] fp16 (grid.z selects)
// ---------------------------------------------------------------------------
struct TArgs { const float* W[4]; __half* T[4]; };

__global__ void transpose_half4(TArgs args)
{
    __shared__ float t[32][33];
    const int tx = threadIdx.x, ty = threadIdx.y;
    const int bx = blockIdx.x * 32, by = blockIdx.y * 32;
    const float* W = args.W[blockIdx.z];
    __half* T = args.T[blockIdx.z];
#pragma unroll
    for (int j = 0; j < 4; j++)
        t[ty + j * 8][tx] = W[(size_t)(by + ty + j * 8) * EMB + bx + tx];
    __syncthreads();
#pragma unroll
    for (int j = 0; j < 4; j++) {
        float v = t[tx][ty + j * 8];
        T[(size_t)(bx + ty + j * 8) * EMB + by + tx] = __float2half_rn(v);
    }
}

// ---------------------------------------------------------------------------
// Merged cast: 3x fp32 -> fp16 (grid.y selects tensor)
// ---------------------------------------------------------------------------
struct CArgs { const float* src[3]; __half* dst[3]; };

__global__ __launch_bounds__(256)
void cast3h(CArgs args)
{
    const int z = blockIdx.y;
    const int i = blockIdx.x * 256 + threadIdx.x;
    float4 v = ((const float4*)args.src[z])[i];
    __half2 a = __floats2half2_rn(v.x, v.y);
    __half2 b = __floats2half2_rn(v.z, v.w);
    uint2 u = {*(uint32_t*)&a, *(uint32_t*)&b};
    ((uint2*)args.dst[z])[i] = u;
}

// ---------------------------------------------------------------------------
// mma.sync fp16 GEMM (single product): C = A @ W^T + bias
// 128x128 block, BK=32, 8 warps (64x32), 3-stage cp.async pipeline.
// grid.z selects (input, weight, bias, scale, dest).
// ---------------------------------------------------------------------------
#define LDT 40
#define TBY (128 * LDT * 2)          // 10240 B per tile
#define BUFB (2 * TBY)               // A|B per stage = 20480 B
#define NSTG 3

struct GArgs {
    const __half* A[3];
    const __half* B[3];
    const float*  bias[3];
    float         scale[3];
    __half*       Ch[3];
    float*        Cf;
};

template <bool HOUT>
__global__ __launch_bounds__(256, 2)
void gemm_ms(GArgs args)
{
    extern __shared__ char smc[];
    const uint32_t sb = smem_to_u32(smc);
    const int tid = threadIdx.x;
    const int wid = tid >> 5, lane = tid & 31;
    const int m0 = blockIdx.y * 128, n0 = blockIdx.x * 128;
    const int z = blockIdx.z;

    const __half* gp[2] = {args.A[z], args.B[z]};
    const int gbase[2] = {m0, n0};

    const int lrow = (lane & 7) + ((lane >> 3) & 1) * 8;
    const int lcol = (lane >> 4) * 8;
    const uint32_t laneoff = (uint32_t)(lrow * (LDT * 2) + lcol * 2);

    const int wm = (wid & 1) * 64;
    const int wn = (wid >> 1) * 32;

    float acc[4][4][4];
#pragma unroll
    for (int i = 0; i < 4; i++)
#pragma unroll
        for (int j = 0; j < 4; j++)
#pragma unroll
            for (int e = 0; e < 4; e++) acc[i][j][e] = 0.0f;

    const int NKC = EMB / 32;   // 32

    // prologue: issue stages 0 and 1
#pragma unroll
    for (int pk = 0; pk < 2; pk++) {
        const uint32_t so = sb + pk * BUFB;
        const int koff = pk * 32;
#pragma unroll
        for (int arr = 0; arr < 2; arr++)
#pragma unroll
            for (int h = 0; h < 2; h++) {
                const int c = tid + h * 256;
                const int row = c >> 2, c4 = c & 3;
                cp16(so + arr * TBY + row * (LDT * 2) + c4 * 16,
                     gp[arr] + (size_t)(gbase[arr] + row) * EMB + koff + c4 * 8);
            }
        cp_commit();
    }

    for (int kc = 0; kc < NKC; kc++) {
        if (kc == NKC - 1) cp_wait<0>(); else cp_wait<1>();
        __syncthreads();

        if (kc + 2 < NKC) {
            const uint32_t so = sb + ((kc + 2) % NSTG) * BUFB;
            const int koff = (kc + 2) * 32;
#pragma unroll
            for (int arr = 0; arr < 2; arr++)
#pragma unroll
                for (int h = 0; h < 2; h++) {
                    const int c = tid + h * 256;
                    const int row = c >> 2, c4 = c & 3;
                    cp16(so + arr * TBY + row * (LDT * 2) + c4 * 16,
                         gp[arr] + (size_t)(gbase[arr] + row) * EMB + koff + c4 * 8);
                }
            cp_commit();
        }

        const uint32_t tb = sb + (kc % NSTG) * BUFB;
#pragma unroll
        for (int ks = 0; ks < 32; ks += 16) {
            uint32_t af[4][4];
#pragma unroll
            for (int i = 0; i < 4; i++)
                ldsm_x4(af[i], tb + (wm + i * 16) * (LDT * 2) + ks * 2 + laneoff);
            uint32_t b0[4], b1[4];
            {
                const uint32_t bo = tb + TBY + wn * (LDT * 2) + ks * 2 + laneoff;
                ldsm_x4(b0, bo);
                ldsm_x4(b1, bo + 16 * (LDT * 2));
            }
#pragma unroll
            for (int i = 0; i < 4; i++) {
                mma_f16(acc[i][0], af[i], b0[0], b0[2]);
                mma_f16(acc[i][1], af[i], b0[1], b0[3]);
                mma_f16(acc[i][2], af[i], b1[0], b1[2]);
                mma_f16(acc[i][3], af[i], b1[1], b1[3]);
            }
        }
    }

    const float scale = args.scale[z];
    const float* bias = args.bias[z];
#pragma unroll
    for (int i = 0; i < 4; i++) {
        const int r = m0 + wm + i * 16 + (lane >> 2);
#pragma unroll
        for (int j = 0; j < 4; j++) {
            const int c = n0 + wn + j * 8 + (lane & 3) * 2;
            const float2 bv = *(const float2*)(bias + c);
            float o00 = (acc[i][j][0] + bv.x) * scale;
            float o01 = (acc[i][j][1] + bv.y) * scale;
            float o10 = (acc[i][j][2] + bv.x) * scale;
            float o11 = (acc[i][j][3] + bv.y) * scale;
            if (HOUT) {
                __half* Ch = args.Ch[z];
                *(__half2*)(Ch + (size_t)r * EMB + c) = __floats2half2_rn(o00, o01);
                *(__half2*)(Ch + (size_t)(r + 8) * EMB + c) = __floats2half2_rn(o10, o11);
            } else {
                *(float2*)(args.Cf + (size_t)r * EMB + c) = make_float2(o00, o01);
                *(float2*)(args.Cf + (size_t)(r + 8) * EMB + c) = make_float2(o10, o11);
            }
        }
    }
}

// ---------------------------------------------------------------------------
// Flash attention, fp16 mma.sync (FA2-style).
// CTA: 128 q rows, 8 warps x 16 rows. 64-key tiles, cp.async double buffer.
// Output: single fp16 array for the O-projection GEMM.
// ---------------------------------------------------------------------------
#define ALD 72
#define AQR 128
#define AKT 64
#define KVB (AKT * ALD * 2)
#define ASM_Q   (AQR * ALD * 2)
#define ASM_K   (ASM_Q)
#define ASM_V   (ASM_K + 2 * KVB)
#define ASM_MSK (ASM_V + 2 * KVB)
#define ASM_TOT (ASM_MSK + 512)

__global__ __launch_bounds__(256)
void attn_mma(const __half* __restrict__ Qh, const __half* __restrict__ Kh,
              const __half* __restrict__ Vh, const int* __restrict__ mask,
              __half* __restrict__ O)
{
    extern __shared__ char sma[];
    const uint32_t sb = smem_to_u32(sma);
    const int* mskp = (const int*)(sma + ASM_MSK);

    const int tid = threadIdx.x, wid = tid >> 5, lane = tid & 31;
    const int qb = blockIdx.x;
    const int n = blockIdx.y >> 4, h = blockIdx.y & 15;
    const int q0 = qb * AQR;

    const size_t qg  = ((size_t)(n * S_LEN + q0)) * EMB + h * HD;
    const size_t kvg = ((size_t)n * S_LEN) * EMB + h * HD;

    const int lrow = (lane & 7) + ((lane >> 3) & 1) * 8;
    const int lcol = (lane >> 4) * 8;
    const uint32_t laneoff = (uint32_t)(lrow * (ALD * 2) + lcol * 2);

#pragma unroll
    for (int i = 0; i < 4; i++) {
        const int c = tid + i * 256;
        const int row = c >> 3, c4 = c & 7;
        cp16(sb + row * (ALD * 2) + c4 * 16, Qh + qg + (size_t)row * EMB + c4 * 8);
    }
#pragma unroll
    for (int i = 0; i < 2; i++) {
        const int c = tid + i * 256;
        const int row = c >> 3, c4 = c & 7;
        cp16(sb + ASM_K + row * (ALD * 2) + c4 * 16,
             Kh + kvg + (size_t)row * EMB + c4 * 8);
        cp16(sb + ASM_V + row * (ALD * 2) + c4 * 16,
             Vh + kvg + (size_t)row * EMB + c4 * 8);
    }
    if (tid < 16)
        cp16(sb + ASM_MSK + tid * 16, mask + n * S_LEN + tid * 4);
    cp_commit();

    uint32_t qa[4][4];
    float o[8][4];
#pragma unroll
    for (int j = 0; j < 8; j++)
#pragma unroll
        for (int e = 0; e < 4; e++) o[j][e] = 0.0f;
    float m0r = -1e30f, m1r = -1e30f, l0 = 0.0f, l1 = 0.0f;

    const int NIT = S_LEN / AKT;
    for (int kt = 0; kt < NIT; kt++) {
        const int buf = kt & 1;
        if (kt + 1 < NIT) {
            const size_t kvo = kvg + (size_t)(kt + 1) * AKT * EMB;
            const uint32_t kd = sb + ASM_K + (buf ^ 1) * KVB;
            const uint32_t vd = sb + ASM_V + (buf ^ 1) * KVB;
#pragma unroll
            for (int i = 0; i < 2; i++) {
                const int c = tid + i * 256;
                const int row = c >> 3, c4 = c & 7;
                cp16(kd + row * (ALD * 2) + c4 * 16, Kh + kvo + (size_t)row * EMB + c4 * 8);
                cp16(vd + row * (ALD * 2) + c4 * 16, Vh + kvo + (size_t)row * EMB + c4 * 8);
            }
            if (tid < 16)
                cp16(sb + ASM_MSK + (buf ^ 1) * 256 + tid * 16,
                     mask + n * S_LEN + (kt + 1) * AKT + tid * 4);
            cp_commit();
            cp_wait<1>();
        } else {
            cp_wait<0>();
        }
        __syncthreads();

        if (kt == 0) {
#pragma unroll
            for (int t = 0; t < 4; t++)
                ldsm_x4(qa[t], sb + (wid * 16) * (ALD * 2) + t * 32 + laneoff);
        }

        const uint32_t kb_ = sb + ASM_K + buf * KVB;
        const uint32_t vb_ = sb + ASM_V + buf * KVB;
        const int* mk = mskp + buf * 64;

        float s[8][4];
#pragma unroll
        for (int j = 0; j < 8; j++)
#pragma unroll
            for (int e = 0; e < 4; e++) s[j][e] = 0.0f;
#pragma unroll
        for (int t = 0; t < 4; t++)
#pragma unroll
            for (int g = 0; g < 4; g++) {
                uint32_t kb[4];
                ldsm_x4(kb, kb_ + (g * 16) * (ALD * 2) + t * 32 + laneoff);
                mma_f16(s[2 * g],     qa[t], kb[0], kb[2]);
                mma_f16(s[2 * g + 1], qa[t], kb[1], kb[3]);
            }

#pragma unroll
        for (int j = 0; j < 8; j++) {
            const int c = j * 8 + (lane & 3) * 2;
            if (mk[c] == 0)     { s[j][0] = -1e20f; s[j][2] = -1e20f; }
            if (mk[c + 1] == 0) { s[j][1] = -1e20f; s[j][3] = -1e20f; }
        }

        float mx0 = s[0][0], mx1 = s[0][2];
#pragma unroll
        for (int j = 0; j < 8; j++) {
            mx0 = fmaxf(mx0, fmaxf(s[j][0], s[j][1]));
            mx1 = fmaxf(mx1, fmaxf(s[j][2], s[j][3]));
        }
        mx0 = fmaxf(mx0, __shfl_xor_sync(0xffffffffu, mx0, 1));
        mx0 = fmaxf(mx0, __shfl_xor_sync(0xffffffffu, mx0, 2));
        mx1 = fmaxf(mx1, __shfl_xor_sync(0xffffffffu, mx1, 1));
        mx1 = fmaxf(mx1, __shfl_xor_sync(0xffffffffu, mx1, 2));
        const float mn0 = fmaxf(m0r, mx0), mn1 = fmaxf(m1r, mx1);
        const float c0 = __expf(m0r - mn0), c1 = __expf(m1r - mn1);
        m0r = mn0; m1r = mn1;
        l0 *= c0; l1 *= c1;
#pragma unroll
        for (int j = 0; j < 8; j++) {
            s[j][0] = __expf(s[j][0] - mn0);
            s[j][1] = __expf(s[j][1] - mn0);
            s[j][2] = __expf(s[j][2] - mn1);
            s[j][3] = __expf(s[j][3] - mn1);
            l0 += s[j][0] + s[j][1];
            l1 += s[j][2] + s[j][3];
            o[j][0] *= c0; o[j][1] *= c0;
            o[j][2] *= c1; o[j][3] *= c1;
        }

#pragma unroll
        for (int t = 0; t < 4; t++) {
            uint32_t pa[4];
            pa[0] = packh2(s[2 * t][0],     s[2 * t][1]);
            pa[1] = packh2(s[2 * t][2],     s[2 * t][3]);
            pa[2] = packh2(s[2 * t + 1][0], s[2 * t + 1][1]);
            pa[3] = packh2(s[2 * t + 1][2], s[2 * t + 1][3]);
#pragma unroll
            for (int jd = 0; jd < 4; jd++) {
                uint32_t vb[4];
                ldsm_x4_t(vb, vb_ + (t * 16 + lrow) * (ALD * 2)
                              + (jd * 16 + lcol) * 2);
                mma_f16(o[2 * jd],     pa, vb[0], vb[1]);
                mma_f16(o[2 * jd + 1], pa, vb[2], vb[3]);
            }
        }
        __syncthreads();
    }

    l0 += __shfl_xor_sync(0xffffffffu, l0, 1);
    l0 += __shfl_xor_sync(0xffffffffu, l0, 2);
    l1 += __shfl_xor_sync(0xffffffffu, l1, 1);
    l1 += __shfl_xor_sync(0xffffffffu, l1, 2);
    const float i0 = 1.0f / l0, i1 = 1.0f / l1;

    const int r0 = q0 + wid * 16 + (lane >> 2);
#pragma unroll
    for (int j = 0; j < 8; j++) {
        const int d = h * HD + j * 8 + (lane & 3) * 2;
        const size_t off0 = (size_t)(n * S_LEN + r0) * EMB + d;
        const size_t off1 = off0 + 8 * EMB;
        *(__half2*)(O + off0) = __floats2half2_rn(o[j][0] * i0, o[j][1] * i0);
        *(__half2*)(O + off1) = __floats2half2_rn(o[j][2] * i1, o[j][3] * i1);
    }
}

// ---------------------------------------------------------------------------
extern "C" void kernel_launch(void* const* d_in, const int* in_sizes, int n_in,
                              void* d_out, int out_size)
{
    const float* values = (const float*)d_in[0];
    const float* keys   = (const float*)d_in[1];
    const float* query  = (const float*)d_in[2];
    const int*   mask   = (const int*)  d_in[3];
    const float* Wv = (const float*)d_in[4];
    const float* bv = (const float*)d_in[5];
    const float* Wk = (const float*)d_in[6];
    const float* bk = (const float*)d_in[7];
    const float* Wq = (const float*)d_in[8];
    const float* bq = (const float*)d_in[9];
    const float* Wo = (const float*)d_in[10];
    const float* bo = (const float*)d_in[11];
    float* out = (float*)d_out;

    __half *wt, *x, *qh, *kh, *vh;
    cudaGetSymbolAddress((void**)&wt, g_wt);
    cudaGetSymbolAddress((void**)&x,  g_x);
    cudaGetSymbolAddress((void**)&qh, g_qh);
    cudaGetSymbolAddress((void**)&kh, g_kh);
    cudaGetSymbolAddress((void**)&vh, g_vh);

    const int gemm_smem = NSTG * BUFB;   // 61440 B
    cudaFuncSetAttribute(gemm_ms<true>,
                         cudaFuncAttributeMaxDynamicSharedMemorySize, gemm_smem);
    cudaFuncSetAttribute(gemm_ms<false>,
                         cudaFuncAttributeMaxDynamicSharedMemorySize, gemm_smem);
    cudaFuncSetAttribute(attn_mma,
                         cudaFuncAttributeMaxDynamicSharedMemorySize, ASM_TOT);

    const size_t WSZ = (size_t)EMB * EMB;
    const int M = NBATCH * S_LEN;

    TArgs ta;
    ta.W[0] = Wq; ta.W[1] = Wk; ta.W[2] = Wv; ta.W[3] = Wo;
    ta.T[0] = wt + 0 * WSZ; ta.T[1] = wt + 1 * WSZ;
    ta.T[2] = wt + 2 * WSZ; ta.T[3] = wt + 3 * WSZ;
    transpose_half4<<<dim3(32, 32, 4), dim3(32, 8)>>>(ta);

    CArgs ca;
    ca.src[0] = query; ca.src[1] = keys; ca.src[2] = values;
    ca.dst[0] = x + 0 * MSZ; ca.dst[1] = x + 1 * MSZ; ca.dst[2] = x + 2 * MSZ;
    cast3h<<<dim3((MSZ / 4) / 256, 3), 256>>>(ca);

    GArgs qkv;
    qkv.A[0] = x + 0 * MSZ; qkv.A[1] = x + 1 * MSZ; qkv.A[2] = x + 2 * MSZ;
    qkv.B[0] = wt + 0 * WSZ; qkv.B[1] = wt + 1 * WSZ; qkv.B[2] = wt + 2 * WSZ;
    qkv.bias[0] = bq; qkv.bias[1] = bk; qkv.bias[2] = bv;
    qkv.scale[0] = 0.03125f; qkv.scale[1] = 1.0f; qkv.scale[2] = 1.0f;
    qkv.Ch[0] = qh; qkv.Ch[1] = kh; qkv.Ch[2] = vh;
    qkv.Cf = nullptr;
    gemm_ms<true><<<dim3(EMB / 128, M / 128, 3), 256, gemm_smem>>>(qkv);

    dim3 agrid(S_LEN / AQR, NBATCH * NH);
    attn_mma<<<agrid, 256, ASM_TOT>>>(qh, kh, vh, mask, x + 0 * MSZ);

    GArgs oproj;
    oproj.A[0] = x + 0 * MSZ; oproj.A[1] = nullptr; oproj.A[2] = nullptr;
    oproj.B[0] = wt + 3 * WSZ; oproj.B[1] = nullptr; oproj.B[2] = nullptr;
    oproj.bias[0] = bo; oproj.bias[1] = nullptr; oproj.bias[2] = nullptr;
    oproj.scale[0] = 1.0f; oproj.scale[1] = 1.0f; oproj.scale[2] = 1.0f;
    oproj.Ch[0] = nullptr; oproj.Ch[1] = nullptr; oproj.Ch[2] = nullptr;
    oproj.Cf = out;
    gemm_ms<false><<<dim3(EMB / 128, M / 128, 1), 256, gemm_smem>>>(oproj);
}